// round 1
// baseline (speedup 1.0000x reference)
#include <cuda_runtime.h>
#include <cuda_bf16.h>

#define Nn  8
#define Cc  64
#define Hh  128
#define Ww  512
#define CoN 64
#define HW  (Hh * Ww)      // 65536
#define NOFF 18            // 2 * K * K

// Scratch: offsets from stage-1 conv, and transposed deform weights [t][c][o].
__device__ float g_off[(size_t)Nn * NOFF * HW];   // ~36 MB
__device__ float g_wt[9 * 64 * 64];               // 144 KB

// ---------------------------------------------------------------------------
// Kernel 0: transpose w_def [o][c][3][3] -> g_wt [t][c][o] (one-time, tiny)
// ---------------------------------------------------------------------------
__global__ void wt_transpose_kernel(const float* __restrict__ wdef) {
    int idx = blockIdx.x * 256 + threadIdx.x;
    if (idx < 9 * 64 * 64) {
        int t = idx % 9;
        int c = (idx / 9) % 64;
        int o = idx / (9 * 64);
        g_wt[(t * 64 + c) * 64 + o] = wdef[idx];
    }
}

// ---------------------------------------------------------------------------
// Kernel 1: offset-predicting 3x3 conv (C=64 -> 18), pad 1, stride 1.
// Block = 128 threads = 128 consecutive x at one (n, y). 18 accumulators/thread.
// Weights in smem, padded to stride 20 floats for LDS.128 vectorization.
// ---------------------------------------------------------------------------
__global__ void __launch_bounds__(128) offset_conv_kernel(
    const float* __restrict__ xin,
    const float* __restrict__ woff,
    const float* __restrict__ boff)
{
    __shared__ __align__(16) float sw[576 * 20];   // [(c*9+tap)][t pad 20] ~45KB
    int tid = threadIdx.x;

    for (int m = tid; m < 18 * 576; m += 128) {
        int t = m / 576;
        int r = m - t * 576;          // c*9 + tap
        sw[r * 20 + t] = woff[m];
    }
    __syncthreads();

    int xo = blockIdx.x * 128 + tid;
    int y  = blockIdx.y;
    int n  = blockIdx.z;

    float acc[18];
#pragma unroll
    for (int t = 0; t < 18; t++) acc[t] = __ldg(&boff[t]);

    const float* xb = xin + (size_t)n * Cc * HW;

    for (int c = 0; c < Cc; c++) {
        const float* xc = xb + c * HW;
#pragma unroll
        for (int i = 0; i < 3; i++) {
            int yy = y + i - 1;
            if (yy < 0 || yy >= Hh) continue;
            const float* row = xc + yy * Ww;
#pragma unroll
            for (int j = 0; j < 3; j++) {
                int xx = xo + j - 1;
                float v = (xx >= 0 && xx < Ww) ? row[xx] : 0.0f;
                const float* wr = &sw[(c * 9 + i * 3 + j) * 20];
                const float4* w4p = (const float4*)wr;
                float4 w0 = w4p[0], w1 = w4p[1], w2 = w4p[2], w3 = w4p[3];
                float2 w4 = *(const float2*)(wr + 16);
                acc[0]  = fmaf(w0.x, v, acc[0]);
                acc[1]  = fmaf(w0.y, v, acc[1]);
                acc[2]  = fmaf(w0.z, v, acc[2]);
                acc[3]  = fmaf(w0.w, v, acc[3]);
                acc[4]  = fmaf(w1.x, v, acc[4]);
                acc[5]  = fmaf(w1.y, v, acc[5]);
                acc[6]  = fmaf(w1.z, v, acc[6]);
                acc[7]  = fmaf(w1.w, v, acc[7]);
                acc[8]  = fmaf(w2.x, v, acc[8]);
                acc[9]  = fmaf(w2.y, v, acc[9]);
                acc[10] = fmaf(w2.z, v, acc[10]);
                acc[11] = fmaf(w2.w, v, acc[11]);
                acc[12] = fmaf(w3.x, v, acc[12]);
                acc[13] = fmaf(w3.y, v, acc[13]);
                acc[14] = fmaf(w3.z, v, acc[14]);
                acc[15] = fmaf(w3.w, v, acc[15]);
                acc[16] = fmaf(w4.x, v, acc[16]);
                acc[17] = fmaf(w4.y, v, acc[17]);
            }
        }
    }

    size_t ob = (size_t)n * NOFF * HW + (size_t)y * Ww + xo;
#pragma unroll
    for (int t = 0; t < 18; t++) g_off[ob + (size_t)t * HW] = acc[t];
}

// ---------------------------------------------------------------------------
// Kernel 2: deformable conv. Block = 256 threads = 256 consecutive x at (n,y).
// Each thread: one output pixel, 64 output-channel accumulators in registers.
// Per tap: stage 64x64 weight slice [c][o] into smem (coalesced from g_wt),
// compute bilinear coefficients once, then loop channels: 4 gathers -> s,
// then 64 FFMA against broadcast smem weights (16 x LDS.128).
// ---------------------------------------------------------------------------
__global__ void __launch_bounds__(256) deform_conv_kernel(
    const float* __restrict__ xin,
    const float* __restrict__ bdef,
    float* __restrict__ out)
{
    __shared__ __align__(16) float sw[4096];   // one tap: [c][o], 16 KB
    __shared__ float sb[64];

    int tid = threadIdx.x;
    if (tid < 64) sb[tid] = bdef[tid];

    int xo = blockIdx.x * 256 + tid;
    int y  = blockIdx.y;
    int n  = blockIdx.z;

    __syncthreads();

    float acc[64];
#pragma unroll
    for (int o = 0; o < 64; o++) acc[o] = sb[o];

    const float* xb   = xin + (size_t)n * Cc * HW;
    const float* offb = g_off + (size_t)n * NOFF * HW + (size_t)y * Ww + xo;

    for (int t = 0; t < 9; t++) {
        __syncthreads();
#pragma unroll
        for (int m = 0; m < 16; m++)
            sw[m * 256 + tid] = g_wt[t * 4096 + m * 256 + tid];
        __syncthreads();

        int i = t / 3, j = t % 3;
        float dy = offb[(size_t)(2 * t) * HW];
        float dx = offb[(size_t)(2 * t + 1) * HW];
        float py = (float)(y + i - 1) + dy;
        float px = (float)(xo + j - 1) + dx;

        float fy = floorf(py), fx = floorf(px);
        float wy1 = py - fy, wx1 = px - fx;
        float wy0 = 1.0f - wy1, wx0 = 1.0f - wx1;
        int iy0 = (int)fy, ix0 = (int)fx;
        int iy1 = iy0 + 1, ix1 = ix0 + 1;

        float gy0 = (iy0 >= 0 && iy0 < Hh) ? wy0 : 0.0f;
        float gy1 = (iy1 >= 0 && iy1 < Hh) ? wy1 : 0.0f;
        float gx0 = (ix0 >= 0 && ix0 < Ww) ? wx0 : 0.0f;
        float gx1 = (ix1 >= 0 && ix1 < Ww) ? wx1 : 0.0f;
        float c00 = gy0 * gx0, c01 = gy0 * gx1;
        float c10 = gy1 * gx0, c11 = gy1 * gx1;

        int yc0 = min(max(iy0, 0), Hh - 1), yc1 = min(max(iy1, 0), Hh - 1);
        int xc0 = min(max(ix0, 0), Ww - 1), xc1 = min(max(ix1, 0), Ww - 1);
        int o00 = yc0 * Ww + xc0, o01 = yc0 * Ww + xc1;
        int o10 = yc1 * Ww + xc0, o11 = yc1 * Ww + xc1;

        const float* p = xb;
        for (int c = 0; c < Cc; c++) {
            float v;
            v = c00 * p[o00];
            v = fmaf(c01, p[o01], v);
            v = fmaf(c10, p[o10], v);
            v = fmaf(c11, p[o11], v);

            const float4* wv = (const float4*)(sw + (c << 6));
#pragma unroll
            for (int q = 0; q < 16; q++) {
                float4 w = wv[q];
                acc[4 * q + 0] = fmaf(w.x, v, acc[4 * q + 0]);
                acc[4 * q + 1] = fmaf(w.y, v, acc[4 * q + 1]);
                acc[4 * q + 2] = fmaf(w.z, v, acc[4 * q + 2]);
                acc[4 * q + 3] = fmaf(w.w, v, acc[4 * q + 3]);
            }
            p += HW;
        }
    }

    size_t ob = (size_t)n * CoN * HW + (size_t)y * Ww + xo;
#pragma unroll
    for (int o = 0; o < 64; o++) out[ob + (size_t)o * HW] = acc[o];
}

// ---------------------------------------------------------------------------
extern "C" void kernel_launch(void* const* d_in, const int* in_sizes, int n_in,
                              void* d_out, int out_size)
{
    const float* x    = (const float*)d_in[0];
    const float* woff = (const float*)d_in[1];
    const float* boff = (const float*)d_in[2];
    const float* wdef = (const float*)d_in[3];
    const float* bdef = (const float*)d_in[4];
    float* out = (float*)d_out;

    wt_transpose_kernel<<<(9 * 64 * 64 + 255) / 256, 256>>>(wdef);
    offset_conv_kernel<<<dim3(Ww / 128, Hh, Nn), 128>>>(x, woff, boff);
    deform_conv_kernel<<<dim3(Ww / 256, Hh, Nn), 256>>>(x, bdef, out);
}